// round 6
// baseline (speedup 1.0000x reference)
#include <cuda_runtime.h>
#include <math.h>

// Problem constants (fixed by the reference)
constexpr int Hc = 512, Wc = 512;
constexpr int Bc = 2, Gc = 4, Fc = 9, Cc = 3;
constexpr int Nn = Hc * Wc;

// Tiling
constexpr int TILE = 32;           // output tile
constexpr int RF   = TILE + 4;     // 36: fM + ew region (2-pixel halo), offset -2
constexpr int RD   = TILE + 2;     // 34: dinv/sig region (1-pixel halo), offset -1
constexpr int FSTR = 9;            // per-pixel stride for fM (9 coprime 32: conflict-free scalar LDS)
constexpr int NP   = RF * RF;      // 1296: ew plane size

constexpr int NTHREADS = 512;

// SMEM layout (floats).  sF is dead after phase 2a; SoA sig planes alias it.
constexpr int OFF_EW = 0;
constexpr int SZ_EW  = 5 * NP;               // 6480 (5 dir planes: self,E,SW,S,SE)
constexpr int OFF_U  = OFF_EW + SZ_EW;       // union region
constexpr int SZ_F   = NP * FSTR + 12;       // 11676 (pad: unconditional region-edge reads)
constexpr int SM_FLOATS = OFF_U + SZ_F;      // 18156
constexpr int SMEM_BYTES = SM_FLOATS * 4;    // 72624 B -> 3 blocks/SM
// SoA planes (alias sF): sP0, sP1, sP2, sDv each RD*RD=1156 floats (4624 total < 11676)

// Pair-packed multiM: per (g,f): pairs (c0,c1)(c2,c3)(c4,c5)(c6,c7)(c8,0)
__constant__ unsigned long long cMp[Gc * Fc * 5];
__device__   unsigned long long g_packM[Gc * Fc * 5];

__device__ __forceinline__ unsigned long long pk2(float lo, float hi) {
    unsigned long long r;
    asm("mov.b64 %0, {%1, %2};" : "=l"(r) : "f"(lo), "f"(hi));
    return r;
}
__device__ __forceinline__ void upk2(float& lo, float& hi, unsigned long long v) {
    asm("mov.b64 {%0, %1}, %2;" : "=f"(lo), "=f"(hi) : "l"(v));
}
__device__ __forceinline__ unsigned long long ffma2(unsigned long long a,
                                                    unsigned long long b,
                                                    unsigned long long c) {
    unsigned long long d;
    asm("fma.rn.f32x2 %0, %1, %2, %3;" : "=l"(d) : "l"(a), "l"(b), "l"(c));
    return d;
}
__device__ __forceinline__ unsigned long long fmul2(unsigned long long a,
                                                    unsigned long long b) {
    unsigned long long d;
    asm("mul.rn.f32x2 %0, %1, %2;" : "=l"(d) : "l"(a), "l"(b));
    return d;
}

__global__ void repack_kernel(const float* __restrict__ M) {
    int i = threadIdx.x;
    if (i < Gc * Fc * 5) {
        int g = i / 45, r = i % 45, f = r / 5, v = r % 5;
        float lo = M[g * 81 + f * 9 + 2 * v];
        float hi = (2 * v + 1 < 9) ? M[g * 81 + f * 9 + 2 * v + 1] : 0.f;
        g_packM[i] = pk2(lo, hi);
    }
}

__device__ __forceinline__ float dot9s(const float a[9], const float* __restrict__ q) {
    float s = a[0] * q[0];
    s = fmaf(a[1], q[1], s);
    s = fmaf(a[2], q[2], s);
    s = fmaf(a[3], q[3], s);
    s = fmaf(a[4], q[4], s);
    s = fmaf(a[5], q[5], s);
    s = fmaf(a[6], q[6], s);
    s = fmaf(a[7], q[7], s);
    s = fmaf(a[8], q[8], s);
    return s;
}

__device__ __forceinline__ float eclip(float s) {
    // NaN-safe: fmaxf(NaN,-10)=-10
    return __expf(fminf(fmaxf(s, -10.f), 10.f));
}

// Packed-FMA feature transform (identical per-element fma order to scalar version).
__device__ __forceinline__ void compute_fm(const float* __restrict__ imgbg, int p,
                                           const unsigned long long* __restrict__ mp,
                                           float* __restrict__ dst) {
    unsigned long long a0 = 0ull, a1 = 0ull, a2 = 0ull, a3 = 0ull, a4 = 0ull;
    float ss = 0.f;
    #pragma unroll
    for (int f = 0; f < 9; f++) {
        const float x = __ldg(imgbg + (size_t)f * Nn + p);
        ss = fmaf(x, x, ss);
        const unsigned long long xx = pk2(x, x);
        a0 = ffma2(xx, mp[f * 5 + 0], a0);
        a1 = ffma2(xx, mp[f * 5 + 1], a1);
        a2 = ffma2(xx, mp[f * 5 + 2], a2);
        a3 = ffma2(xx, mp[f * 5 + 3], a3);
        a4 = ffma2(xx, mp[f * 5 + 4], a4);
    }
    const float inv = rsqrtf(fmaxf(ss, 1e-24f));
    const unsigned long long ii = pk2(inv, inv);
    float lo, hi;
    upk2(lo, hi, fmul2(a0, ii)); dst[0] = lo; dst[1] = hi;
    upk2(lo, hi, fmul2(a1, ii)); dst[2] = lo; dst[3] = hi;
    upk2(lo, hi, fmul2(a2, ii)); dst[4] = lo; dst[5] = hi;
    upk2(lo, hi, fmul2(a3, ii)); dst[6] = lo; dst[7] = hi;
    upk2(lo, hi, fmul2(a4, ii)); dst[8] = lo;
}

__global__ void __launch_bounds__(NTHREADS, 3)
glr_fused_kernel(const float* __restrict__ img,
                 const float* __restrict__ sig,
                 float* __restrict__ out)
{
    extern __shared__ float sm[];
    float* __restrict__ sEw = sm + OFF_EW;   // 5 planes of NP
    float* __restrict__ sF  = sm + OFF_U;    // fM features (dead after phase 2a)
    float* __restrict__ sP0 = sm + OFF_U;                 // aliases sF
    float* __restrict__ sP1 = sm + OFF_U + RD * RD;
    float* __restrict__ sP2 = sm + OFF_U + 2 * RD * RD;
    float* __restrict__ sDv = sm + OFF_U + 3 * RD * RD;

    const int tid = threadIdx.x;
    const int bg  = blockIdx.z;
    const int g   = bg & (Gc - 1);
    const int x0  = blockIdx.x * TILE;
    const int y0  = blockIdx.y * TILE;
    const bool interior = (blockIdx.x >= 1) && (blockIdx.x <= 14) &&
                          (blockIdx.y >= 1) && (blockIdx.y <= 14);

    const float* __restrict__ imgbg = img + (size_t)bg * Fc * Nn;
    const float* __restrict__ sigbg = sig + (size_t)bg * Cc * Nn;
    const unsigned long long* __restrict__ mp = cMp + g * 45;

    // ---------------- Phase 1: fM over 36x36 region ----------------
    if (interior) {
        const int pbase = (y0 - 2) * Wc + (x0 - 2);
        for (int idx = tid; idx < NP; idx += NTHREADS) {
            const int ry = idx / RF;
            const int rx = idx - ry * RF;
            compute_fm(imgbg, pbase + ry * Wc + rx, mp, sF + idx * FSTR);
        }
    } else {
        for (int idx = tid; idx < NP; idx += NTHREADS) {
            const int ry = idx / RF;
            const int rx = idx - ry * RF;
            const int gy = y0 - 2 + ry;
            const int gx = x0 - 2 + rx;
            float* __restrict__ dst = sF + idx * FSTR;
            if ((unsigned)gy < (unsigned)Hc && (unsigned)gx < (unsigned)Wc) {
                compute_fm(imgbg, gy * Wc + gx, mp, dst);
            } else {
                #pragma unroll
                for (int v = 0; v < 9; v++) dst[v] = 0.f;
            }
        }
    }
    __syncthreads();

    // ------- Phase 2a: 5-dir ew (self,E,SW,S,SE) over rows 0..34, plane layout -------
    if (interior) {
        // Pixel-pairing: each task = 2 adjacent pixels (rx2, rx2+1). 7 fM vectors / 10 dots.
        // Out-of-window reads land in valid smem or the 12-float pad; the affected ew slots
        // (E/SE of col35, SW of col0, anything in row35) are never consumed downstream.
        for (int t = tid; t < 35 * 18; t += NTHREADS) {
            const int ry  = t / 18;
            const int rx2 = (t - ry * 18) * 2;
            const int idx = ry * RF + rx2;
            const float* __restrict__ pf = sF + idx * FSTR;            // (ry, rx2)
            const float* __restrict__ pb = pf + (RF - 1) * FSTR;       // (ry+1, rx2-1)

            unsigned long long c[9];                                   // (a1[f], a2[f])
            unsigned long long sAcc = 0ull;                            // (a1·a1, a2·a2)
            float s12 = 0.f;                                           // a1·a2 (E of p1)
            #pragma unroll
            for (int f = 0; f < 9; f++) {
                const float lo = pf[f];
                const float hi = pf[FSTR + f];
                c[f] = pk2(lo, hi);
                sAcc = ffma2(c[f], c[f], sAcc);
                s12 = fmaf(lo, hi, s12);
            }
            float s11, s22; upk2(s11, s22, sAcc);

            // E of p2 = a2·a3
            float e2 = 0.f;
            #pragma unroll
            for (int f = 0; f < 9; f++) {
                float lo, hi; upk2(lo, hi, c[f]);
                e2 = fmaf(hi, pf[2 * FSTR + f], e2);
            }

            // b-row dots, two at a time via f32x2
            unsigned long long t0 = 0ull, t1 = 0ull, t2 = 0ull, t3 = 0ull;
            #pragma unroll
            for (int f = 0; f < 9; f++) {
                t0 = ffma2(c[f], pk2(pb[f],            pb[f]),            t0); // (SW1, -)
                t1 = ffma2(c[f], pk2(pb[FSTR + f],     pb[FSTR + f]),     t1); // (S1, SW2)
                t2 = ffma2(c[f], pk2(pb[2 * FSTR + f], pb[2 * FSTR + f]), t2); // (SE1, S2)
                t3 = ffma2(c[f], pk2(pb[3 * FSTR + f], pb[3 * FSTR + f]), t3); // (-, SE2)
            }
            float sw1, xx0; upk2(sw1, xx0, t0);
            float s1,  sw2; upk2(s1,  sw2, t1);
            float se1, s2;  upk2(se1, s2,  t2);
            float xx1, se2; upk2(xx1, se2, t3);
            (void)xx0; (void)xx1;

            // conflict-free float2 plane writes (idx even)
            *reinterpret_cast<float2*>(sEw + idx)          = make_float2(eclip(s11), eclip(s22));
            *reinterpret_cast<float2*>(sEw + NP + idx)     = make_float2(eclip(s12), eclip(e2));
            *reinterpret_cast<float2*>(sEw + 2 * NP + idx) = make_float2(eclip(sw1), eclip(sw2));
            *reinterpret_cast<float2*>(sEw + 3 * NP + idx) = make_float2(eclip(s1),  eclip(s2));
            *reinterpret_cast<float2*>(sEw + 4 * NP + idx) = make_float2(eclip(se1), eclip(se2));
        }
    } else {
        for (int idx = tid; idx < (RF - 1) * RF; idx += NTHREADS) {
            const int ry = idx / RF;
            const int rx = idx - ry * RF;
            const int gy = y0 - 2 + ry;
            const int gx = x0 - 2 + rx;
            if (((unsigned)gy < (unsigned)Hc) && ((unsigned)gx < (unsigned)Wc)) {
                const float* __restrict__ pf = sF + idx * FSTR;
                float a[9];
                #pragma unroll
                for (int f = 0; f < 9; f++) a[f] = pf[f];
                float s = a[0] * a[0];
                #pragma unroll
                for (int f = 1; f < 9; f++) s = fmaf(a[f], a[f], s);
                sEw[idx] = eclip(s);
                sEw[NP + idx] = (rx + 1 < RF && (unsigned)(gx + 1) < (unsigned)Wc)
                        ? eclip(dot9s(a, pf + FSTR)) : 0.f;
                sEw[2 * NP + idx] = (rx - 1 >= 0 &&
                         (unsigned)(gy + 1) < (unsigned)Hc && (unsigned)(gx - 1) < (unsigned)Wc)
                        ? eclip(dot9s(a, pf + (RF - 1) * FSTR)) : 0.f;
                sEw[3 * NP + idx] = ((unsigned)(gy + 1) < (unsigned)Hc)
                        ? eclip(dot9s(a, pf + RF * FSTR)) : 0.f;
                sEw[4 * NP + idx] = (rx + 1 < RF &&
                         (unsigned)(gy + 1) < (unsigned)Hc && (unsigned)(gx + 1) < (unsigned)Wc)
                        ? eclip(dot9s(a, pf + (RF + 1) * FSTR)) : 0.f;
            } else {
                sEw[idx] = 0.f; sEw[NP + idx] = 0.f; sEw[2 * NP + idx] = 0.f;
                sEw[3 * NP + idx] = 0.f; sEw[4 * NP + idx] = 0.f;
            }
        }
    }
    __syncthreads();

    // ------- Phase 2b: deg -> dinv gather + prescaled sig (SoA), over 34x34 -------
    // NOTE: sP*/sDv alias sF; sF fully consumed by phase 2a.
    if (interior) {
        const int pbase = (y0 - 1) * Wc + (x0 - 1);
        for (int idx = tid; idx < RD * RD; idx += NTHREADS) {
            const int ly = idx / RD;
            const int lx = idx - ly * RD;
            const int r = (ly + 1) * RF + (lx + 1);
            float deg = sEw[r] + sEw[NP + r] + sEw[2 * NP + r] + sEw[3 * NP + r] + sEw[4 * NP + r];
            deg += sEw[4 * NP + r - RF - 1];  // NW = SE of up-left
            deg += sEw[3 * NP + r - RF];      // N  = S  of up
            deg += sEw[2 * NP + r - RF + 1];  // NE = SW of up-right
            deg += sEw[NP + r - 1];           // W  = E  of left
            const float dinv = rsqrtf(deg);   // deg >= 1
            const int p = pbase + ly * Wc + lx;
            sP0[idx] = __ldg(sigbg + p) * dinv;
            sP1[idx] = __ldg(sigbg + Nn + p) * dinv;
            sP2[idx] = __ldg(sigbg + 2 * Nn + p) * dinv;
            sDv[idx] = dinv;
        }
    } else {
        for (int idx = tid; idx < RD * RD; idx += NTHREADS) {
            const int ly = idx / RD;
            const int lx = idx - ly * RD;
            const int gy = y0 - 1 + ly;
            const int gx = x0 - 1 + lx;
            const bool inb = ((unsigned)gy < (unsigned)Hc) && ((unsigned)gx < (unsigned)Wc);
            const int r = (ly + 1) * RF + (lx + 1);
            float dinv = 0.f;
            if (inb) {
                float deg = sEw[r] + sEw[NP + r] + sEw[2 * NP + r] + sEw[3 * NP + r] + sEw[4 * NP + r];
                deg += sEw[4 * NP + r - RF - 1];
                deg += sEw[3 * NP + r - RF];
                deg += sEw[2 * NP + r - RF + 1];
                deg += sEw[NP + r - 1];
                dinv = rsqrtf(deg);
            }
            const int p = gy * Wc + gx;
            sP0[idx] = inb ? __ldg(sigbg + p) * dinv          : 0.f;
            sP1[idx] = inb ? __ldg(sigbg + Nn + p) * dinv     : 0.f;
            sP2[idx] = inb ? __ldg(sigbg + 2 * Nn + p) * dinv : 0.f;
            sDv[idx] = dinv;
        }
    }
    __syncthreads();

    // ---------------- Phase 3: aggregation + output ----------------
    // out_c = s_c - dp * S_c,  S_c = sum_t ew_t * s'_{c,nb(t)},  s_c = s'_c * (1/dp)
    float* __restrict__ outbg = out + (size_t)bg * Cc * Nn;
    for (int idx = tid; idx < TILE * TILE; idx += NTHREADS) {
        const int ly = idx >> 5;
        const int lx = idx & 31;
        const int r = (ly + 2) * RF + (lx + 2);   // region coords
        const int d = (ly + 1) * RD + (lx + 1);   // RD coords

        const float dp = sDv[d];
        unsigned long long S01 = 0ull;
        float S2 = 0.f;

        #define GLR_ACC(nn, ww) do {                                        \
            const float _w = (ww);                                          \
            S01 = ffma2(pk2(sP0[nn], sP1[nn]), pk2(_w, _w), S01);            \
            S2  = fmaf(sP2[nn], _w, S2);                                    \
        } while (0)

        GLR_ACC(d - RD - 1, sEw[4 * NP + r - RF - 1]);  // NW
        GLR_ACC(d - RD,     sEw[3 * NP + r - RF]);      // N
        GLR_ACC(d - RD + 1, sEw[2 * NP + r - RF + 1]);  // NE
        GLR_ACC(d - 1,      sEw[NP + r - 1]);           // W
        // center (keep s' for output)
        const float c0 = sP0[d], c1 = sP1[d], c2 = sP2[d];
        {
            const float w = sEw[r];
            S01 = ffma2(pk2(c0, c1), pk2(w, w), S01);
            S2  = fmaf(c2, w, S2);
        }
        GLR_ACC(d + 1,      sEw[NP + r]);               // E
        GLR_ACC(d + RD - 1, sEw[2 * NP + r]);           // SW
        GLR_ACC(d + RD,     sEw[3 * NP + r]);           // S
        GLR_ACC(d + RD + 1, sEw[4 * NP + r]);           // SE
        #undef GLR_ACC

        float S0, S1; upk2(S0, S1, S01);
        const float inv = __fdividef(1.0f, dp);         // dp in (0,1], MUFU.RCP
        const int p = (y0 + ly) * Wc + (x0 + lx);
        outbg[p]          = fmaf(-dp, S0, c0 * inv);
        outbg[Nn + p]     = fmaf(-dp, S1, c1 * inv);
        outbg[2 * Nn + p] = fmaf(-dp, S2, c2 * inv);
    }
}

extern "C" void kernel_launch(void* const* d_in, const int* in_sizes, int n_in,
                              void* d_out, int out_size) {
    const float* img = (const float*)d_in[0];  // (B,G,F,H,W)
    const float* sig = (const float*)d_in[1];  // (B,G,C,H,W)
    const float* M   = (const float*)d_in[2];  // (G,F,F)
    float* out = (float*)d_out;

    cudaFuncSetAttribute(glr_fused_kernel,
                         cudaFuncAttributeMaxDynamicSharedMemorySize, SMEM_BYTES);

    repack_kernel<<<1, 192>>>(M);
    void* packed_ptr = nullptr;
    cudaGetSymbolAddress(&packed_ptr, g_packM);
    cudaMemcpyToSymbolAsync(cMp, packed_ptr, Gc * Fc * 5 * sizeof(unsigned long long),
                            0, cudaMemcpyDeviceToDevice, 0);

    dim3 grid(Wc / TILE, Hc / TILE, Bc * Gc);
    glr_fused_kernel<<<grid, NTHREADS, SMEM_BYTES>>>(img, sig, out);
}

// round 7
// speedup vs baseline: 1.0267x; 1.0267x over previous
#include <cuda_runtime.h>
#include <math.h>

// Problem constants (fixed by the reference)
constexpr int Hc = 512, Wc = 512;
constexpr int Bc = 2, Gc = 4, Fc = 9, Cc = 3;
constexpr int Nn = Hc * Wc;

// Tiling
constexpr int TILE = 32;           // output tile
constexpr int RF   = TILE + 4;     // 36: fM + ew region (2-pixel halo), offset -2
constexpr int RD   = TILE + 2;     // 34: dinv/sig region (1-pixel halo), offset -1
constexpr int FSTR = 9;            // per-pixel stride for fM (9 coprime 32: conflict-free scalar LDS)
constexpr int NP   = RF * RF;      // 1296: ew plane size

constexpr int NTHREADS = 512;

// SMEM layout (floats).  sF is dead after phase 2a; SoA sig planes alias it.
constexpr int OFF_EW = 0;
constexpr int SZ_EW  = 5 * NP;               // 6480 (5 dir planes: self,E,SW,S,SE)
constexpr int OFF_U  = OFF_EW + SZ_EW;       // union region
constexpr int SZ_F   = NP * FSTR + 12;       // 11676 (pad: unconditional region-edge reads)
constexpr int SM_FLOATS = OFF_U + SZ_F;      // 18156
constexpr int SMEM_BYTES = SM_FLOATS * 4;    // 72624 B -> 3 blocks/SM
// SoA planes (alias sF): sP0, sP1, sP2, sDv each RD*RD=1156 floats (4624 total < 11676)

// Pair-packed multiM: per (g,f): pairs (c0,c1)(c2,c3)(c4,c5)(c6,c7)(c8,0)
__constant__ unsigned long long cMp[Gc * Fc * 5];
__device__   unsigned long long g_packM[Gc * Fc * 5];

__device__ __forceinline__ unsigned long long pk2(float lo, float hi) {
    unsigned long long r;
    asm("mov.b64 %0, {%1, %2};" : "=l"(r) : "f"(lo), "f"(hi));
    return r;
}
__device__ __forceinline__ void upk2(float& lo, float& hi, unsigned long long v) {
    asm("mov.b64 {%0, %1}, %2;" : "=f"(lo), "=f"(hi) : "l"(v));
}
__device__ __forceinline__ unsigned long long ffma2(unsigned long long a,
                                                    unsigned long long b,
                                                    unsigned long long c) {
    unsigned long long d;
    asm("fma.rn.f32x2 %0, %1, %2, %3;" : "=l"(d) : "l"(a), "l"(b), "l"(c));
    return d;
}
__device__ __forceinline__ unsigned long long fmul2(unsigned long long a,
                                                    unsigned long long b) {
    unsigned long long d;
    asm("mul.rn.f32x2 %0, %1, %2;" : "=l"(d) : "l"(a), "l"(b));
    return d;
}

__global__ void repack_kernel(const float* __restrict__ M) {
    int i = threadIdx.x;
    if (i < Gc * Fc * 5) {
        int g = i / 45, r = i % 45, f = r / 5, v = r % 5;
        float lo = M[g * 81 + f * 9 + 2 * v];
        float hi = (2 * v + 1 < 9) ? M[g * 81 + f * 9 + 2 * v + 1] : 0.f;
        g_packM[i] = pk2(lo, hi);
    }
}

__device__ __forceinline__ float dot9s(const float a[9], const float* __restrict__ q) {
    float s = a[0] * q[0];
    s = fmaf(a[1], q[1], s);
    s = fmaf(a[2], q[2], s);
    s = fmaf(a[3], q[3], s);
    s = fmaf(a[4], q[4], s);
    s = fmaf(a[5], q[5], s);
    s = fmaf(a[6], q[6], s);
    s = fmaf(a[7], q[7], s);
    s = fmaf(a[8], q[8], s);
    return s;
}

__device__ __forceinline__ float eclip(float s) {
    // NaN-safe: fmaxf(NaN,-10)=-10
    return __expf(fminf(fmaxf(s, -10.f), 10.f));
}

// Packed-FMA feature transform (identical per-element fma order to scalar version).
// Writes the 9 fM floats to dst and returns the self-similarity dot (sum of squares).
__device__ __forceinline__ float compute_fm(const float* __restrict__ imgbg, int p,
                                            const unsigned long long* __restrict__ mp,
                                            float* __restrict__ dst) {
    unsigned long long a0 = 0ull, a1 = 0ull, a2 = 0ull, a3 = 0ull, a4 = 0ull;
    float ss = 0.f;
    #pragma unroll
    for (int f = 0; f < 9; f++) {
        const float x = __ldg(imgbg + (size_t)f * Nn + p);
        ss = fmaf(x, x, ss);
        const unsigned long long xx = pk2(x, x);
        a0 = ffma2(xx, mp[f * 5 + 0], a0);
        a1 = ffma2(xx, mp[f * 5 + 1], a1);
        a2 = ffma2(xx, mp[f * 5 + 2], a2);
        a3 = ffma2(xx, mp[f * 5 + 3], a3);
        a4 = ffma2(xx, mp[f * 5 + 4], a4);
    }
    const float inv = rsqrtf(fmaxf(ss, 1e-24f));
    const unsigned long long ii = pk2(inv, inv);
    float v0, v1, v2, v3, v4, v5, v6, v7, v8, hi;
    upk2(v0, v1, fmul2(a0, ii)); dst[0] = v0; dst[1] = v1;
    upk2(v2, v3, fmul2(a1, ii)); dst[2] = v2; dst[3] = v3;
    upk2(v4, v5, fmul2(a2, ii)); dst[4] = v4; dst[5] = v5;
    upk2(v6, v7, fmul2(a3, ii)); dst[6] = v6; dst[7] = v7;
    upk2(v8, hi, fmul2(a4, ii)); dst[8] = v8; (void)hi;
    // self-dot from registers (no smem reads)
    float s = v0 * v0;
    s = fmaf(v1, v1, s); s = fmaf(v2, v2, s); s = fmaf(v3, v3, s);
    s = fmaf(v4, v4, s); s = fmaf(v5, v5, s); s = fmaf(v6, v6, s);
    s = fmaf(v7, v7, s); s = fmaf(v8, v8, s);
    return s;
}

__global__ void __launch_bounds__(NTHREADS, 3)
glr_fused_kernel(const float* __restrict__ img,
                 const float* __restrict__ sig,
                 float* __restrict__ out)
{
    extern __shared__ float sm[];
    float* __restrict__ sEw = sm + OFF_EW;   // 5 planes of NP
    float* __restrict__ sF  = sm + OFF_U;    // fM features (dead after phase 2a)
    float* __restrict__ sP0 = sm + OFF_U;                 // aliases sF
    float* __restrict__ sP1 = sm + OFF_U + RD * RD;
    float* __restrict__ sP2 = sm + OFF_U + 2 * RD * RD;
    float* __restrict__ sDv = sm + OFF_U + 3 * RD * RD;

    const int tid = threadIdx.x;
    const int bg  = blockIdx.z;
    const int g   = bg & (Gc - 1);
    const int x0  = blockIdx.x * TILE;
    const int y0  = blockIdx.y * TILE;
    const bool interior = (blockIdx.x >= 1) && (blockIdx.x <= 14) &&
                          (blockIdx.y >= 1) && (blockIdx.y <= 14);

    const float* __restrict__ imgbg = img + (size_t)bg * Fc * Nn;
    const float* __restrict__ sigbg = sig + (size_t)bg * Cc * Nn;
    const unsigned long long* __restrict__ mp = cMp + g * 45;

    // ------- Phase 1: fM over 36x36 region + self-similarity plane -------
    if (interior) {
        const int pbase = (y0 - 2) * Wc + (x0 - 2);
        for (int idx = tid; idx < NP; idx += NTHREADS) {
            const int ry = idx / RF;
            const int rx = idx - ry * RF;
            const float s = compute_fm(imgbg, pbase + ry * Wc + rx, mp, sF + idx * FSTR);
            sEw[idx] = eclip(s);
        }
    } else {
        for (int idx = tid; idx < NP; idx += NTHREADS) {
            const int ry = idx / RF;
            const int rx = idx - ry * RF;
            const int gy = y0 - 2 + ry;
            const int gx = x0 - 2 + rx;
            float* __restrict__ dst = sF + idx * FSTR;
            if ((unsigned)gy < (unsigned)Hc && (unsigned)gx < (unsigned)Wc) {
                const float s = compute_fm(imgbg, gy * Wc + gx, mp, dst);
                sEw[idx] = eclip(s);
            } else {
                #pragma unroll
                for (int v = 0; v < 9; v++) dst[v] = 0.f;
                sEw[idx] = 0.f;
            }
        }
    }
    __syncthreads();

    // ------- Phase 2a: 4-dir ew (E,SW,S,SE) over rows 0..34, plane layout -------
    if (interior) {
        // No predicates: region-edge out-of-window reads land in valid smem or the
        // 12-float pad; affected ew slots (E col35, SW col0, SE col35) never consumed.
        for (int idx = tid; idx < (RF - 1) * RF; idx += NTHREADS) {
            const float* __restrict__ pf = sF + idx * FSTR;
            float a[9];
            #pragma unroll
            for (int f = 0; f < 9; f++) a[f] = pf[f];
            sEw[NP + idx]     = eclip(dot9s(a, pf + FSTR));              // E
            sEw[2 * NP + idx] = eclip(dot9s(a, pf + (RF - 1) * FSTR));   // SW
            sEw[3 * NP + idx] = eclip(dot9s(a, pf + RF * FSTR));         // S
            sEw[4 * NP + idx] = eclip(dot9s(a, pf + (RF + 1) * FSTR));   // SE
        }
    } else {
        for (int idx = tid; idx < (RF - 1) * RF; idx += NTHREADS) {
            const int ry = idx / RF;
            const int rx = idx - ry * RF;
            const int gy = y0 - 2 + ry;
            const int gx = x0 - 2 + rx;
            if (((unsigned)gy < (unsigned)Hc) && ((unsigned)gx < (unsigned)Wc)) {
                const float* __restrict__ pf = sF + idx * FSTR;
                float a[9];
                #pragma unroll
                for (int f = 0; f < 9; f++) a[f] = pf[f];
                sEw[NP + idx] = (rx + 1 < RF && (unsigned)(gx + 1) < (unsigned)Wc)
                        ? eclip(dot9s(a, pf + FSTR)) : 0.f;
                sEw[2 * NP + idx] = (rx - 1 >= 0 &&
                         (unsigned)(gy + 1) < (unsigned)Hc && (unsigned)(gx - 1) < (unsigned)Wc)
                        ? eclip(dot9s(a, pf + (RF - 1) * FSTR)) : 0.f;
                sEw[3 * NP + idx] = ((unsigned)(gy + 1) < (unsigned)Hc)
                        ? eclip(dot9s(a, pf + RF * FSTR)) : 0.f;
                sEw[4 * NP + idx] = (rx + 1 < RF &&
                         (unsigned)(gy + 1) < (unsigned)Hc && (unsigned)(gx + 1) < (unsigned)Wc)
                        ? eclip(dot9s(a, pf + (RF + 1) * FSTR)) : 0.f;
            } else {
                sEw[NP + idx] = 0.f; sEw[2 * NP + idx] = 0.f;
                sEw[3 * NP + idx] = 0.f; sEw[4 * NP + idx] = 0.f;
            }
        }
    }
    __syncthreads();

    // ------- Phase 2b: deg -> dinv gather + prescaled sig (SoA), over 34x34 -------
    // NOTE: sP*/sDv alias sF; sF fully consumed by phase 2a.
    if (interior) {
        const int pbase = (y0 - 1) * Wc + (x0 - 1);
        for (int idx = tid; idx < RD * RD; idx += NTHREADS) {
            const int ly = idx / RD;
            const int lx = idx - ly * RD;
            const int r = (ly + 1) * RF + (lx + 1);
            float deg = sEw[r] + sEw[NP + r] + sEw[2 * NP + r] + sEw[3 * NP + r] + sEw[4 * NP + r];
            deg += sEw[4 * NP + r - RF - 1];  // NW = SE of up-left
            deg += sEw[3 * NP + r - RF];      // N  = S  of up
            deg += sEw[2 * NP + r - RF + 1];  // NE = SW of up-right
            deg += sEw[NP + r - 1];           // W  = E  of left
            const float dinv = rsqrtf(deg);   // deg >= 1
            const int p = pbase + ly * Wc + lx;
            sP0[idx] = __ldg(sigbg + p) * dinv;
            sP1[idx] = __ldg(sigbg + Nn + p) * dinv;
            sP2[idx] = __ldg(sigbg + 2 * Nn + p) * dinv;
            sDv[idx] = dinv;
        }
    } else {
        for (int idx = tid; idx < RD * RD; idx += NTHREADS) {
            const int ly = idx / RD;
            const int lx = idx - ly * RD;
            const int gy = y0 - 1 + ly;
            const int gx = x0 - 1 + lx;
            const bool inb = ((unsigned)gy < (unsigned)Hc) && ((unsigned)gx < (unsigned)Wc);
            const int r = (ly + 1) * RF + (lx + 1);
            float dinv = 0.f;
            if (inb) {
                float deg = sEw[r] + sEw[NP + r] + sEw[2 * NP + r] + sEw[3 * NP + r] + sEw[4 * NP + r];
                deg += sEw[4 * NP + r - RF - 1];
                deg += sEw[3 * NP + r - RF];
                deg += sEw[2 * NP + r - RF + 1];
                deg += sEw[NP + r - 1];
                dinv = rsqrtf(deg);
            }
            const int p = gy * Wc + gx;
            sP0[idx] = inb ? __ldg(sigbg + p) * dinv          : 0.f;
            sP1[idx] = inb ? __ldg(sigbg + Nn + p) * dinv     : 0.f;
            sP2[idx] = inb ? __ldg(sigbg + 2 * Nn + p) * dinv : 0.f;
            sDv[idx] = dinv;
        }
    }
    __syncthreads();

    // ---------------- Phase 3: aggregation + output (scalar fma) ----------------
    // out_c = s_c - dp * S_c,  S_c = sum_t ew_t * s'_{c,nb(t)},  s_c = s'_c * (1/dp)
    float* __restrict__ outbg = out + (size_t)bg * Cc * Nn;
    for (int idx = tid; idx < TILE * TILE; idx += NTHREADS) {
        const int ly = idx >> 5;
        const int lx = idx & 31;
        const int r = (ly + 2) * RF + (lx + 2);   // region coords
        const int d = (ly + 1) * RD + (lx + 1);   // RD coords

        const float dp = sDv[d];
        float S0 = 0.f, S1 = 0.f, S2 = 0.f;

        #define GLR_ACC(nn, ww) do {                \
            const float _w = (ww);                  \
            const int _n = (nn);                    \
            S0 = fmaf(sP0[_n], _w, S0);             \
            S1 = fmaf(sP1[_n], _w, S1);             \
            S2 = fmaf(sP2[_n], _w, S2);             \
        } while (0)

        GLR_ACC(d - RD - 1, sEw[4 * NP + r - RF - 1]);  // NW
        GLR_ACC(d - RD,     sEw[3 * NP + r - RF]);      // N
        GLR_ACC(d - RD + 1, sEw[2 * NP + r - RF + 1]);  // NE
        GLR_ACC(d - 1,      sEw[NP + r - 1]);           // W
        const float c0 = sP0[d], c1 = sP1[d], c2 = sP2[d];
        {
            const float w = sEw[r];                     // self
            S0 = fmaf(c0, w, S0); S1 = fmaf(c1, w, S1); S2 = fmaf(c2, w, S2);
        }
        GLR_ACC(d + 1,      sEw[NP + r]);               // E
        GLR_ACC(d + RD - 1, sEw[2 * NP + r]);           // SW
        GLR_ACC(d + RD,     sEw[3 * NP + r]);           // S
        GLR_ACC(d + RD + 1, sEw[4 * NP + r]);           // SE
        #undef GLR_ACC

        const float inv = __fdividef(1.0f, dp);         // dp in (0,1], MUFU.RCP
        const int p = (y0 + ly) * Wc + (x0 + lx);
        outbg[p]          = fmaf(-dp, S0, c0 * inv);
        outbg[Nn + p]     = fmaf(-dp, S1, c1 * inv);
        outbg[2 * Nn + p] = fmaf(-dp, S2, c2 * inv);
    }
}

extern "C" void kernel_launch(void* const* d_in, const int* in_sizes, int n_in,
                              void* d_out, int out_size) {
    const float* img = (const float*)d_in[0];  // (B,G,F,H,W)
    const float* sig = (const float*)d_in[1];  // (B,G,C,H,W)
    const float* M   = (const float*)d_in[2];  // (G,F,F)
    float* out = (float*)d_out;

    cudaFuncSetAttribute(glr_fused_kernel,
                         cudaFuncAttributeMaxDynamicSharedMemorySize, SMEM_BYTES);

    repack_kernel<<<1, 192>>>(M);
    void* packed_ptr = nullptr;
    cudaGetSymbolAddress(&packed_ptr, g_packM);
    cudaMemcpyToSymbolAsync(cMp, packed_ptr, Gc * Fc * 5 * sizeof(unsigned long long),
                            0, cudaMemcpyDeviceToDevice, 0);

    dim3 grid(Wc / TILE, Hc / TILE, Bc * Gc);
    glr_fused_kernel<<<grid, NTHREADS, SMEM_BYTES>>>(img, sig, out);
}